// round 13
// baseline (speedup 1.0000x reference)
#include <cuda_runtime.h>
#include <math.h>

#define BB 16      // batch
#define TT 1024    // sequence
#define JJ 128     // input dim
#define HH 64      // hidden (complex) dim

// Per-(b, segment) ZERO-STATE carry C (complex, 64 h) + ready flags.
__device__ __align__(16) float2 g_C[BB * 8 * HH];
__device__ unsigned g_flag[BB * 8];

// ---------------------------------------------------------------------------
// helpers
// ---------------------------------------------------------------------------
__device__ __forceinline__ unsigned tf32bits(float v) {
    unsigned r;
    asm("cvt.rna.tf32.f32 %0, %1;" : "=r"(r) : "f"(v));
    return r;
}
__device__ __forceinline__ void mma_tf32(float& d0, float& d1, float& d2, float& d3,
                                         unsigned a0, unsigned a1, unsigned a2, unsigned a3,
                                         unsigned b0, unsigned b1) {
    asm("mma.sync.aligned.m16n8k8.row.col.f32.tf32.tf32.f32 "
        "{%0,%1,%2,%3}, {%4,%5,%6,%7}, {%8,%9}, {%0,%1,%2,%3};"
        : "+f"(d0), "+f"(d1), "+f"(d2), "+f"(d3)
        : "r"(a0), "r"(a1), "r"(a2), "r"(a3), "r"(b0), "r"(b1));
}
__device__ __forceinline__ unsigned fbits(float v) { return __float_as_uint(v); }
__device__ __forceinline__ void cpa16(void* smem_dst, const void* gsrc) {
    unsigned d = (unsigned)__cvta_generic_to_shared(smem_dst);
    asm volatile("cp.async.cg.shared.global [%0], [%1], 16;"
                 :: "r"(d), "l"(gsrc) : "memory");
}

// ---------------------------------------------------------------------------
// Prologue: reset lookback flags (graph-replay safe; ~0.2us measured).
// ---------------------------------------------------------------------------
__global__ void reset_kernel() { g_flag[threadIdx.x] = 0u; }

// ---------------------------------------------------------------------------
// K1: fused GEMM (3xTF32) + segment scan + MLP decoupled lookback.
// Grid 128 = 16 b x 8 t-segments (128 t each), 256 threads, ALL RESIDENT.
// GEMM/staging identical to round 12. After publishing its zero-state carry,
// each block waits for its <=7 predecessors with PARALLEL flag polls (one L2
// round trip per retry) + PARALLEL carry loads, Horner in registers, then
// phase C writes FINAL outputs (no fixup pass, out written exactly once).
// ---------------------------------------------------------------------------
#define XST 132
#define K1_SMEM_BYTES ((128 * XST + 64 * XST) * 4)   // 101376 B

__global__ __launch_bounds__(256) void fused_kernel(const float* __restrict__ x,
                                                    const float* __restrict__ Bm,
                                                    const float* __restrict__ nu,
                                                    const float* __restrict__ theta,
                                                    float* __restrict__ out) {
    extern __shared__ __align__(16) float sm[];
    float* xraw = sm;                    // [t 0..127][j 0..127] stride 132
    float* braw = sm + 128 * XST;        // [h 0..63][j 0..127]  stride 132

    __shared__ float Vr_s[4 * 64], Vi_s[4 * 64];
    __shared__ float Wr_s[4 * 64], Wi_s[4 * 64];
    __shared__ float Ssr[64], Ssi[64];

    const int tid  = threadIdx.x;
    const int lane = tid & 31;
    const int wid  = tid >> 5;
    const int wt   = wid >> 1;          // 0..3 -> 32 t
    const int wh   = wid & 1;           // 0..1 -> 32 h
    const int b    = blockIdx.x >> 3;
    const int ts   = blockIdx.x & 7;
    const int t0   = ts * 128;
    const int lr   = lane >> 2;         // 0..7
    const int lc   = lane & 3;          // 0..3

    // ---- Stage raw x and B via cp.async (16B chunks) ----
#pragma unroll
    for (int i = 0; i < 16; ++i) {
        int f  = tid + 256 * i;
        int t  = f >> 5;
        int jq = f & 31;
        cpa16(&xraw[t * XST + jq * 4], x + ((size_t)(b * TT + t0 + t) * JJ + jq * 4));
    }
#pragma unroll
    for (int i = 0; i < 8; ++i) {
        int f  = tid + 256 * i;
        int h  = f >> 5;
        int jq = f & 31;
        cpa16(&braw[h * XST + jq * 4], Bm + (size_t)h * JJ + jq * 4);
    }
    asm volatile("cp.async.commit_group;");
    asm volatile("cp.async.wait_group 0;" ::: "memory");
    __syncthreads();

    float acc[2][4][4];
#pragma unroll
    for (int m = 0; m < 2; ++m)
#pragma unroll
        for (int n = 0; n < 4; ++n)
#pragma unroll
            for (int q = 0; q < 4; ++q) acc[m][n][q] = 0.f;

    // ---- 16 k-steps; tf32 split at fragment load ----
#pragma unroll 4
    for (int ks = 0; ks < 16; ++ks) {
        const int j0 = ks * 8 + lc;
        unsigned ah[2][4], al[2][4];
#pragma unroll
        for (int m = 0; m < 2; ++m) {
            int r0 = (wt * 32 + m * 16 + lr) * XST + j0;
            float a0 = xraw[r0];
            float a1 = xraw[r0 + 8 * XST];
            float a2 = xraw[r0 + 4];
            float a3 = xraw[r0 + 8 * XST + 4];
            ah[m][0] = tf32bits(a0); al[m][0] = fbits(a0 - __uint_as_float(ah[m][0]));
            ah[m][1] = tf32bits(a1); al[m][1] = fbits(a1 - __uint_as_float(ah[m][1]));
            ah[m][2] = tf32bits(a2); al[m][2] = fbits(a2 - __uint_as_float(ah[m][2]));
            ah[m][3] = tf32bits(a3); al[m][3] = fbits(a3 - __uint_as_float(ah[m][3]));
        }
#pragma unroll
        for (int n = 0; n < 4; ++n) {
            int rb = (wh * 32 + n * 8 + lr) * XST + j0;
            float b0 = braw[rb];
            float b1 = braw[rb + 4];
            unsigned bh0 = tf32bits(b0), bl0 = fbits(b0 - __uint_as_float(bh0));
            unsigned bh1 = tf32bits(b1), bl1 = fbits(b1 - __uint_as_float(bh1));
#pragma unroll
            for (int m = 0; m < 2; ++m) {
                mma_tf32(acc[m][n][0], acc[m][n][1], acc[m][n][2], acc[m][n][3],
                         ah[m][0], ah[m][1], ah[m][2], ah[m][3], bh0, bh1);
                mma_tf32(acc[m][n][0], acc[m][n][1], acc[m][n][2], acc[m][n][3],
                         ah[m][0], ah[m][1], ah[m][2], ah[m][3], bl0, bl1);
                mma_tf32(acc[m][n][0], acc[m][n][1], acc[m][n][2], acc[m][n][3],
                         al[m][0], al[m][1], al[m][2], al[m][3], bh0, bh1);
            }
        }
    }
    __syncthreads();

    // Stage D = Bx into smem as [t][h], stride 65 (aliases staging region).
    float* sD = sm;   // 128 * 65 floats
#pragma unroll
    for (int m = 0; m < 2; ++m)
#pragma unroll
        for (int n = 0; n < 4; ++n) {
            int tr = wt * 32 + m * 16 + lr;
            int hc = wh * 32 + n * 8 + 2 * lc;
            sD[tr * 65 + hc]           = acc[m][n][0];
            sD[tr * 65 + hc + 1]       = acc[m][n][1];
            sD[(tr + 8) * 65 + hc]     = acc[m][n][2];
            sD[(tr + 8) * 65 + hc + 1] = acc[m][n][3];
        }
    __syncthreads();

    // ---- Segment-local scan ----
    const int h = tid & 63;
    const int c = tid >> 6;             // 0..3: 32-step chunk

    const float mag = expf(-expf(nu[h]));
    float sn, cs;
    sincosf(theta[h], &sn, &cs);
    const float Lr = mag * cs;
    const float Li = mag * sn;

    // P = lam^32 (all threads; phase C needs it)
    float Pr = Lr, Pi = Li;
#pragma unroll
    for (int s = 0; s < 5; ++s) {
        float nr = Pr * Pr - Pi * Pi;
        float ni = 2.f * Pr * Pi;
        Pr = nr; Pi = ni;
    }

    float u[32];
#pragma unroll
    for (int k = 0; k < 32; ++k) u[k] = sD[(c * 32 + k) * 65 + h];

    // Phase A: local chunk scan from zero -> chunk value V
    float yr = 0.f, yi = 0.f;
#pragma unroll
    for (int k = 0; k < 32; ++k) {
        float nyr = fmaf(Lr, yr, fmaf(-Li, yi, u[k]));
        float nyi = fmaf(Lr, yi, Li * yr);
        yr = nyr; yi = nyi;
    }
    Vr_s[c * 64 + h] = yr;
    Vi_s[c * 64 + h] = yi;
    __syncthreads();

    // Combine (tid<64): chunk prefixes + zero-state carry C; publish.
    if (tid < 64) {
        float wr = 0.f, wi = 0.f;
        Wr_s[h] = 0.f; Wi_s[h] = 0.f;
#pragma unroll
        for (int cc = 1; cc < 4; ++cc) {
            float vr = Vr_s[(cc - 1) * 64 + h];
            float vi = Vi_s[(cc - 1) * 64 + h];
            float nwr = vr + (Pr * wr - Pi * wi);
            float nwi = vi + (Pr * wi + Pi * wr);
            wr = nwr; wi = nwi;
            Wr_s[cc * 64 + h] = wr;
            Wi_s[cc * 64 + h] = wi;
        }
        float vr = Vr_s[3 * 64 + h];
        float vi = Vi_s[3 * 64 + h];
        float Cr = vr + (Pr * wr - Pi * wi);
        float Ci = vi + (Pr * wi + Pi * wr);
        g_C[(b * 8 + ts) * 64 + h] = make_float2(Cr, Ci);
        __threadfence();
    }
    __syncthreads();
    if (tid == 0) {
        asm volatile("st.release.gpu.b32 [%0], %1;"
                     :: "l"(&g_flag[b * 8 + ts]), "r"(1u) : "memory");
    }

    // MLP lookback (tid<64): parallel flag polls, parallel carry loads,
    // register Horner S = Q^ts + sum Q^(ts-1-g) C_g ; Q = lam^128 = P^4.
    if (tid < 64) {
        float Sr = 1.f, Si = 0.f;
        if (ts > 0) {
            const unsigned* fbase = &g_flag[b * 8];
            for (;;) {
                unsigned all = 1u;
#pragma unroll
                for (int g = 0; g < 7; ++g) {
                    if (g < ts) {
                        unsigned f;
                        asm volatile("ld.relaxed.gpu.b32 %0, [%1];"
                                     : "=r"(f) : "l"(fbase + g) : "memory");
                        all &= f;
                    }
                }
                if (all) break;
                __nanosleep(100);
            }
            __threadfence();   // acquire: flags seen -> carries visible

            float2 cg[7];
#pragma unroll
            for (int g = 0; g < 7; ++g)
                cg[g] = (g < ts) ? g_C[(b * 8 + g) * 64 + h]
                                 : make_float2(0.f, 0.f);

            float Q2r = Pr * Pr - Pi * Pi;
            float Q2i = 2.f * Pr * Pi;
            float Qr = Q2r * Q2r - Q2i * Q2i;
            float Qi = 2.f * Q2r * Q2i;
#pragma unroll
            for (int g = 0; g < 7; ++g) {
                if (g < ts) {
                    float nr = Qr * Sr - Qi * Si + cg[g].x;
                    float ni = Qr * Si + Qi * Sr + cg[g].y;
                    Sr = nr; Si = ni;
                }
            }
        }
        Ssr[h] = Sr; Ssi[h] = Si;
    }
    __syncthreads();

    // Phase C: incoming state for chunk c = W_c + P^c * S ; write FINAL out.
    {
        float Sr = Ssr[h], Si = Ssi[h];
        float pcr = 1.f, pci = 0.f;
#pragma unroll
        for (int d = 0; d < 2; ++d) {
            if ((c >> d) & 1) {
                float br = (d == 0) ? Pr : (Pr * Pr - Pi * Pi);
                float bi = (d == 0) ? Pi : (2.f * Pr * Pi);
                float nr = pcr * br - pci * bi;
                float ni = pcr * bi + pci * br;
                pcr = nr; pci = ni;
            }
        }
        yr = Wr_s[c * 64 + h] + (pcr * Sr - pci * Si);
        yi = Wi_s[c * 64 + h] + (pcr * Si + pci * Sr);
    }
    float* op = out + (b * TT + t0 + c * 32) * (2 * HH) + h;
#pragma unroll
    for (int k = 0; k < 32; ++k) {
        float nyr = fmaf(Lr, yr, fmaf(-Li, yi, u[k]));
        float nyi = fmaf(Lr, yi, Li * yr);
        yr = nyr; yi = nyi;
        op[k * 128]      = yr;   // re at [b,t,h]
        op[k * 128 + 64] = yi;   // im at [b,t,H+h]
    }
}

// ---------------------------------------------------------------------------
extern "C" void kernel_launch(void* const* d_in, const int* in_sizes, int n_in,
                              void* d_out, int out_size) {
    const float* x     = (const float*)d_in[0];   // [16,1024,128]
    const float* Bm    = (const float*)d_in[1];   // [64,128]
    const float* nu    = (const float*)d_in[2];   // [64]
    const float* theta = (const float*)d_in[3];   // [64]
    float* out = (float*)d_out;                   // [16,1024,128]

    cudaFuncSetAttribute(fused_kernel,
                         cudaFuncAttributeMaxDynamicSharedMemorySize,
                         K1_SMEM_BYTES);
    reset_kernel<<<1, 128>>>();
    fused_kernel<<<128, 256, K1_SMEM_BYTES>>>(x, Bm, nu, theta, out);
}

// round 14
// speedup vs baseline: 1.2166x; 1.2166x over previous
#include <cuda_runtime.h>
#include <math.h>

#define BB 16      // batch
#define TT 1024    // sequence
#define JJ 128     // input dim
#define HH 64      // hidden (complex) dim

// Scratch: Bx in [b][h][t] layout (contiguous t rows for the scan).
__device__ float g_Bxt[BB * HH * TT];   // 4 MB static scratch

// ---------------------------------------------------------------------------
// tf32 helpers
// ---------------------------------------------------------------------------
__device__ __forceinline__ unsigned tf32bits(float v) {
    unsigned r;
    asm("cvt.rna.tf32.f32 %0, %1;" : "=r"(r) : "f"(v));
    return r;
}
__device__ __forceinline__ void mma_tf32(float& d0, float& d1, float& d2, float& d3,
                                         unsigned a0, unsigned a1, unsigned a2, unsigned a3,
                                         unsigned b0, unsigned b1) {
    asm("mma.sync.aligned.m16n8k8.row.col.f32.tf32.tf32.f32 "
        "{%0,%1,%2,%3}, {%4,%5,%6,%7}, {%8,%9}, {%0,%1,%2,%3};"
        : "+f"(d0), "+f"(d1), "+f"(d2), "+f"(d3)
        : "r"(a0), "r"(a1), "r"(a2), "r"(a3), "r"(b0), "r"(b1));
}
__device__ __forceinline__ unsigned fbits(float v) { return __float_as_uint(v); }

// ---------------------------------------------------------------------------
// Kernel 1: Bxt[b][h][t] = sum_j B[h][j] * x[b][t][j]   (3xTF32 tensor-core)
// ROUND-4 VERSION VERBATIM (validated 17.1us total).
// Grid 256 = 16 b x 16 t-segs of 64. Block 128 thr = 4 warps in 2x2 (t,h);
// warp tile 32t x 32h. K=128 in 2 chunks of 64 staged as tf32 hi/lo.
// ---------------------------------------------------------------------------
#define KST 68
#define GEMM_SMEM_BYTES (4 * 64 * KST * 4)   // 69632 B

__global__ __launch_bounds__(128) void gemm_kernel(const float* __restrict__ x,
                                                   const float* __restrict__ Bm) {
    extern __shared__ __align__(16) float sm[];
    float* xhi = sm;                  // [t 0..63][j 0..63] stride 68
    float* xlo = sm + 64 * KST;
    float* bhi = sm + 2 * 64 * KST;   // [h 0..63][j 0..63] stride 68
    float* blo = sm + 3 * 64 * KST;

    const int tid  = threadIdx.x;
    const int lane = tid & 31;
    const int wid  = tid >> 5;
    const int wt   = wid >> 1;        // 0..1 -> t offset 32*wt
    const int wh   = wid & 1;         // 0..1 -> h offset 32*wh
    const int b    = blockIdx.x >> 4;
    const int t0   = (blockIdx.x & 15) * 64;

    const int lr = lane >> 2;         // 0..7
    const int lc = lane & 3;          // 0..3

    float acc[2][4][4];
#pragma unroll
    for (int m = 0; m < 2; ++m)
#pragma unroll
        for (int n = 0; n < 4; ++n)
#pragma unroll
            for (int q = 0; q < 4; ++q) acc[m][n][q] = 0.f;

    const float4* x4 = reinterpret_cast<const float4*>(x);
    const float4* B4 = reinterpret_cast<const float4*>(Bm);

    for (int kc = 0; kc < 2; ++kc) {
        if (kc) __syncthreads();
        // Stage x chunk: 64 t x 16 float4, split hi/lo
#pragma unroll
        for (int i = 0; i < 8; ++i) {
            int f  = tid + 128 * i;
            int t  = f >> 4;
            int jq = f & 15;
            float4 v = x4[(b * TT + t0 + t) * 32 + kc * 16 + jq];
            float4 hv, lv;
            hv.x = __uint_as_float(tf32bits(v.x)); lv.x = v.x - hv.x;
            hv.y = __uint_as_float(tf32bits(v.y)); lv.y = v.y - hv.y;
            hv.z = __uint_as_float(tf32bits(v.z)); lv.z = v.z - hv.z;
            hv.w = __uint_as_float(tf32bits(v.w)); lv.w = v.w - hv.w;
            *reinterpret_cast<float4*>(&xhi[t * KST + jq * 4]) = hv;
            *reinterpret_cast<float4*>(&xlo[t * KST + jq * 4]) = lv;
        }
        // Stage B chunk: 64 h x 16 float4, split hi/lo
#pragma unroll
        for (int i = 0; i < 8; ++i) {
            int f  = tid + 128 * i;
            int h  = f >> 4;
            int jq = f & 15;
            float4 v = B4[h * 32 + kc * 16 + jq];
            float4 hv, lv;
            hv.x = __uint_as_float(tf32bits(v.x)); lv.x = v.x - hv.x;
            hv.y = __uint_as_float(tf32bits(v.y)); lv.y = v.y - hv.y;
            hv.z = __uint_as_float(tf32bits(v.z)); lv.z = v.z - hv.z;
            hv.w = __uint_as_float(tf32bits(v.w)); lv.w = v.w - hv.w;
            *reinterpret_cast<float4*>(&bhi[h * KST + jq * 4]) = hv;
            *reinterpret_cast<float4*>(&blo[h * KST + jq * 4]) = lv;
        }
        __syncthreads();

#pragma unroll
        for (int ks = 0; ks < 8; ++ks) {
            const int j0 = ks * 8;
            unsigned ah[2][4], al[2][4];
#pragma unroll
            for (int m = 0; m < 2; ++m) {
                int base = (wt * 32 + m * 16 + lr) * KST + j0 + lc;
                ah[m][0] = fbits(xhi[base]);
                ah[m][1] = fbits(xhi[base + 8 * KST]);
                ah[m][2] = fbits(xhi[base + 4]);
                ah[m][3] = fbits(xhi[base + 8 * KST + 4]);
                al[m][0] = fbits(xlo[base]);
                al[m][1] = fbits(xlo[base + 8 * KST]);
                al[m][2] = fbits(xlo[base + 4]);
                al[m][3] = fbits(xlo[base + 8 * KST + 4]);
            }
#pragma unroll
            for (int n = 0; n < 4; ++n) {
                int hb = (wh * 32 + n * 8 + lr) * KST + j0 + lc;
                unsigned bh0 = fbits(bhi[hb]);
                unsigned bh1 = fbits(bhi[hb + 4]);
                unsigned bl0 = fbits(blo[hb]);
                unsigned bl1 = fbits(blo[hb + 4]);
#pragma unroll
                for (int m = 0; m < 2; ++m) {
                    mma_tf32(acc[m][n][0], acc[m][n][1], acc[m][n][2], acc[m][n][3],
                             ah[m][0], ah[m][1], ah[m][2], ah[m][3], bh0, bh1);
                    mma_tf32(acc[m][n][0], acc[m][n][1], acc[m][n][2], acc[m][n][3],
                             ah[m][0], ah[m][1], ah[m][2], ah[m][3], bl0, bl1);
                    mma_tf32(acc[m][n][0], acc[m][n][1], acc[m][n][2], acc[m][n][3],
                             al[m][0], al[m][1], al[m][2], al[m][3], bh0, bh1);
                }
            }
        }
    }
    __syncthreads();

    // Epilogue: stage D into smem as [h][t] (stride 68), then coalesced
    // float4 writes of g_Bxt[b][h][t] rows.
    float* sD = sm;   // 64 * 68 floats, aliases xhi (safe after sync)
#pragma unroll
    for (int m = 0; m < 2; ++m)
#pragma unroll
        for (int n = 0; n < 4; ++n) {
            int tr = wt * 32 + m * 16 + lr;
            int hc = wh * 32 + n * 8 + 2 * lc;
            sD[hc * KST + tr]            = acc[m][n][0];
            sD[(hc + 1) * KST + tr]      = acc[m][n][1];
            sD[hc * KST + tr + 8]        = acc[m][n][2];
            sD[(hc + 1) * KST + tr + 8]  = acc[m][n][3];
        }
    __syncthreads();
    {
        int h  = tid >> 1;
        int tq = tid & 1;
        float* dst = &g_Bxt[(b * HH + h) * TT + t0 + tq * 32];
        const float* srcp = &sD[h * KST + tq * 32];
#pragma unroll
        for (int i = 0; i < 8; ++i) {
            *reinterpret_cast<float4*>(dst + i * 4) =
                *reinterpret_cast<const float4*>(srcp + i * 4);
        }
    }
}

// ---------------------------------------------------------------------------
// Kernel 2: complex linear scan  y_t = lam*y_{t-1} + Bx_t,  y_{-1} = 1.
// HALF-WIDTH BLOCKS: (b, 4h) x 256 thr, grid 256 -> ~2 blocks/SM so barrier
// drains of one block overlap with issue of the other. Per-thread work and
// carry algebra identical to the validated round-2/4 version.
// 64 chunks of 16 t per h; 8 warps = 4 h x 2 halves; KS + bridge.
// ---------------------------------------------------------------------------
#define CST 5   // carry row stride (4 h + pad)

__global__ __launch_bounds__(256) void scan_kernel(const float* __restrict__ nu,
                                                   const float* __restrict__ theta,
                                                   float* __restrict__ out) {
    __shared__ float svr[64 * CST];
    __shared__ float svi[64 * CST];
    __shared__ float sbr[4], sbi[4];

    const int tid = threadIdx.x;
    const int tg  = tid >> 2;          // 0..63  t-chunk (16 steps)
    const int hl  = tid & 3;           // 0..3
    const int b   = blockIdx.y;
    const int hb  = blockIdx.x * 4;
    const int h   = hb + hl;

    const float mag = expf(-expf(nu[h]));
    float sn0, cs0;
    sincosf(theta[h], &sn0, &cs0);
    const float lr = mag * cs0;
    const float li = mag * sn0;

    // Load 16 inputs (4 x LDG.128)
    float u[16];
    const float4* src =
        reinterpret_cast<const float4*>(&g_Bxt[(b * HH + h) * TT + tg * 16]);
#pragma unroll
    for (int q = 0; q < 4; ++q) {
        float4 v = src[q];
        u[4 * q + 0] = v.x; u[4 * q + 1] = v.y;
        u[4 * q + 2] = v.z; u[4 * q + 3] = v.w;
    }

    // Phase A: local scan from zero -> chunk value V
    float yr = 0.f, yi = 0.f;
#pragma unroll
    for (int k = 0; k < 16; ++k) {
        float nyr = fmaf(lr, yr, fmaf(-li, yi, u[k]));
        float nyi = fmaf(lr, yi, li * yr);
        yr = nyr; yi = nyi;
    }
    svr[tg * CST + hl] = yr;
    svi[tg * CST + hl] = yi;
    __syncthreads();

    // Phase B: warp (hw, half) scans chunks half*32 + lane of h = hb+hw.
    const int lane = tid & 31;
    const int wid  = tid >> 5;          // 0..7
    const int hw   = wid & 3;
    const int half = wid >> 2;
    const int c    = half * 32 + lane;

    const int   h2   = hb + hw;
    const float mag2 = expf(-expf(nu[h2]));
    float sn2, cs2;
    sincosf(theta[h2], &sn2, &cs2);
    float ar = mag2 * cs2;
    float ai = mag2 * sn2;

    // P = lam^16 via 4 squarings
    float pr = ar, pi = ai;
#pragma unroll
    for (int s = 0; s < 4; ++s) {
        float nr = pr * pr - pi * pi;
        float ni = 2.f * pr * pi;
        pr = nr; pi = ni;
    }
    float Pr[5], Pi[5];
    Pr[0] = pr; Pi[0] = pi;
#pragma unroll
    for (int d = 1; d < 5; ++d) {
        Pr[d] = Pr[d - 1] * Pr[d - 1] - Pi[d - 1] * Pi[d - 1];
        Pi[d] = 2.f * Pr[d - 1] * Pi[d - 1];
    }
    const float P32r = Pr[4] * Pr[4] - Pi[4] * Pi[4];
    const float P32i = 2.f * Pr[4] * Pi[4];

    float Vr = svr[c * CST + hw];
    float Vi = svi[c * CST + hw];
    // Kogge-Stone inclusive scan: V_i <- V_i + P^(2^d) * V_{i-2^d}
#pragma unroll
    for (int d = 0; d < 5; ++d) {
        int sh = 1 << d;
        float orr = __shfl_up_sync(0xffffffffu, Vr, sh);
        float oii = __shfl_up_sync(0xffffffffu, Vi, sh);
        if (lane >= sh) {
            float nVr = Vr + (Pr[d] * orr - Pi[d] * oii);
            float nVi = Vi + (Pr[d] * oii + Pi[d] * orr);
            Vr = nVr; Vi = nVi;
        }
    }
    // Bridge: inclusive total of low half -> high half's base
    if (half == 0 && lane == 31) { sbr[hw] = Vr; sbi[hw] = Vi; }
    __syncthreads();

    float Br_ = 1.f, Bi_ = 0.f;           // Base = E_{-1} = 1 for low half
    if (half) {                            // Base = E_31 = P^32 + Vtilde_31
        Br_ = P32r + sbr[hw];
        Bi_ = P32i + sbi[hw];
    }
    // Exclusive local prefix
    float Wr = __shfl_up_sync(0xffffffffu, Vr, 1);
    float Wi = __shfl_up_sync(0xffffffffu, Vi, 1);
    if (lane == 0) { Wr = 0.f; Wi = 0.f; }
    // P^lane
    float qr = 1.f, qi = 0.f;
#pragma unroll
    for (int d = 0; d < 5; ++d) {
        if ((lane >> d) & 1) {
            float nr = qr * Pr[d] - qi * Pi[d];
            float ni = qr * Pi[d] + qi * Pr[d];
            qr = nr; qi = ni;
        }
    }
    // Incoming state for chunk c: S = W + P^lane * Base
    svr[c * CST + hw] = Wr + (qr * Br_ - qi * Bi_);
    svi[c * CST + hw] = Wi + (qr * Bi_ + qi * Br_);
    __syncthreads();

    // Phase C: re-run chunk with true incoming state.
    yr = svr[tg * CST + hl];
    yi = svi[tg * CST + hl];
    float* op = out + (b * TT + tg * 16) * (2 * HH) + h;
#pragma unroll
    for (int k = 0; k < 16; ++k) {
        float nyr = fmaf(lr, yr, fmaf(-li, yi, u[k]));
        float nyi = fmaf(lr, yi, li * yr);
        yr = nyr; yi = nyi;
        op[k * 128]      = yr;   // re at [b,t,h]
        op[k * 128 + 64] = yi;   // im at [b,t,H+h]
    }
}

// ---------------------------------------------------------------------------
extern "C" void kernel_launch(void* const* d_in, const int* in_sizes, int n_in,
                              void* d_out, int out_size) {
    const float* x     = (const float*)d_in[0];   // [16,1024,128]
    const float* Bm    = (const float*)d_in[1];   // [64,128]
    const float* nu    = (const float*)d_in[2];   // [64]
    const float* theta = (const float*)d_in[3];   // [64]
    float* out = (float*)d_out;                   // [16,1024,128]

    cudaFuncSetAttribute(gemm_kernel,
                         cudaFuncAttributeMaxDynamicSharedMemorySize,
                         GEMM_SMEM_BYTES);
    gemm_kernel<<<256, 128, GEMM_SMEM_BYTES>>>(x, Bm);
    scan_kernel<<<dim3(16, 16), 256>>>(nu, theta, out);
}